// round 10
// baseline (speedup 1.0000x reference)
#include <cuda_runtime.h>
#include <cstdint>

#define CRF_B 1024
#define CRF_S 512
#define CRF_T 64
#define CRF_M 255     // forward: t in [1,255]; backward: t in [511,256]
#define E_REG 48      // E rows register-resident; rows 48..63 live in shared

// Static device scratch (no allocation)
__device__ float g_mid[2][CRF_B][CRF_T];
__device__ float g_ub[CRF_B];
__device__ float g_partial[CRF_B];
__device__ unsigned int g_done[CRF_B];
__device__ unsigned int g_count = 0;

__device__ __forceinline__ float ex2f(float x) {
    float y; asm("ex2.approx.ftz.f32 %0, %1;" : "=f"(y) : "f"(x)); return y;
}
__device__ __forceinline__ float lg2f(float x) {
    float y; asm("lg2.approx.f32 %0, %1;" : "=f"(y) : "f"(x)); return y;
}

// grid = (B, 2): y==0 forward half (+unary/binary), y==1 backward half.
// 64 threads per CTA, thread j owns state j. Log-domain (base-2) recurrence,
// thread-0 anchor, two barriers per step (R1 structure). E split 48 reg / 16 smem
// so 14 CTAs fit per SM -> the whole 2048-CTA grid runs in ONE wave.
__global__ void __launch_bounds__(CRF_T, 14) crf_scan_kernel(
    const float* __restrict__ inputs,        // [B, S, T]
    const float* __restrict__ trans,         // [T, T]
    const unsigned char* __restrict__ masks, // [B, S]
    const int* __restrict__ tags,            // [B, S]
    float* __restrict__ out, int out_size)
{
    const int b = blockIdx.x;
    const int dir = blockIdx.y;
    const int j = threadIdx.x;
    const float L = 1.4426950408889634f;  // log2(e)

    __shared__ __align__(16) float p_sh[CRF_T];
    __shared__ float Esh[CRF_T - E_REG][CRF_T];   // rows 48..63 of this CTA's E
    __shared__ float Msh;
    __shared__ float red[CRF_T];
    __shared__ unsigned char mask_sh[CRF_S];
    __shared__ unsigned int flag_sh;

    const float* xb = inputs + (size_t)b * CRF_S * CRF_T;
    const unsigned char* mk = masks + (size_t)b * CRF_S;

    for (int s = j; s < CRF_S; s += CRF_T) mask_sh[s] = mk[s];
    __syncthreads();

    float vj;            // final base-2 log element of this half-scan
    float E[E_REG];      // register-resident part of E (48 rows)

    if (dir == 0) {
        // ---------------- forward half ----------------
        const int* tg = tags + (size_t)b * CRF_S;

        // unary + binary partial sums over the FULL sequence (fwd CTA only)
        float ub = 0.f;
        for (int s = j; s < CRF_S; s += CRF_T) {
            if (!mask_sh[s]) {
                int ts = tg[s];
                ub += xb[s * CRF_T + ts];
                if (s >= 1) ub += trans[tg[s - 1] * CRF_T + ts];
            }
        }

        // E[i] = e^{trans[i][j]}: rows 0..47 in regs, rows 48..63 in shared
#pragma unroll
        for (int i = 0; i < E_REG; i++)
            E[i] = ex2f(L * trans[i * CRF_T + j]);
        for (int i = E_REG; i < CRF_T; i++)
            Esh[i - E_REG][j] = ex2f(L * trans[i * CRF_T + j]);

        float bj = L * xb[j];
        if (j == 0) Msh = bj;
        __syncthreads();

        float xnext = xb[CRF_T + j];

#pragma unroll 1
        for (int t = 1; t <= CRF_M; t++) {
            float M = Msh;
            p_sh[j] = ex2f(bj - M);
            float xt = xnext;
            unsigned char m = mask_sh[t];
            __syncthreads();
            if (t < CRF_M) xnext = xb[(t + 1) * CRF_T + j];

            float s0 = 0.f, s1 = 0.f, s2 = 0.f, s3 = 0.f;
            const float4* p4 = reinterpret_cast<const float4*>(p_sh);
#pragma unroll
            for (int k = 0; k < E_REG / 4; k++) {
                float4 p = p4[k];
                s0 = fmaf(p.x, E[4 * k + 0], s0);
                s1 = fmaf(p.y, E[4 * k + 1], s1);
                s2 = fmaf(p.z, E[4 * k + 2], s2);
                s3 = fmaf(p.w, E[4 * k + 3], s3);
            }
#pragma unroll
            for (int c = 0; c < CRF_T - E_REG; c += 4) {
                float4 p = p4[(E_REG + c) / 4];
                s0 = fmaf(p.x, Esh[c + 0][j], s0);
                s1 = fmaf(p.y, Esh[c + 1][j], s1);
                s2 = fmaf(p.z, Esh[c + 2][j], s2);
                s3 = fmaf(p.w, Esh[c + 3][j], s3);
            }
            float ssum = (s0 + s1) + (s2 + s3);

            float bn = fmaf(xt, L, M + lg2f(ssum));
            if (!m) bj = bn;
            if (j == 0) Msh = bj;
            __syncthreads();
        }
        vj = bj;

        red[j] = ub;
        __syncthreads();
        if (j == 0) {
            float su = 0.f;
            for (int i = 0; i < CRF_T; i++) su += red[i];
            g_ub[b] = su;
        }
    } else {
        // ---------------- backward half ----------------
        // r recurrence: c'_j = M + lg2( sum_i u_i * E[j][i] ),
        // u_i = 2^{L*x_ti + c_i - M}. Thread j needs ROW j of E.
#pragma unroll
        for (int i = 0; i < E_REG; i++)
            E[i] = ex2f(L * trans[j * CRF_T + i]);
        for (int i = E_REG; i < CRF_T; i++)
            Esh[i - E_REG][j] = ex2f(L * trans[j * CRF_T + i]);

        float cj = 0.f;
        if (j == 0) Msh = 0.f;
        __syncthreads();

        float xnext = xb[(CRF_S - 1) * CRF_T + j];

#pragma unroll 1
        for (int t = CRF_S - 1; t > CRF_M; t--) {
            float M = Msh;
            float xt = xnext;
            unsigned char m = mask_sh[t];
            p_sh[j] = ex2f(fmaf(L, xt, cj - M));
            __syncthreads();
            if (t > CRF_M + 1) xnext = xb[(t - 1) * CRF_T + j];

            float s0 = 0.f, s1 = 0.f, s2 = 0.f, s3 = 0.f;
            const float4* p4 = reinterpret_cast<const float4*>(p_sh);
#pragma unroll
            for (int k = 0; k < E_REG / 4; k++) {
                float4 p = p4[k];
                s0 = fmaf(p.x, E[4 * k + 0], s0);
                s1 = fmaf(p.y, E[4 * k + 1], s1);
                s2 = fmaf(p.z, E[4 * k + 2], s2);
                s3 = fmaf(p.w, E[4 * k + 3], s3);
            }
#pragma unroll
            for (int c = 0; c < CRF_T - E_REG; c += 4) {
                float4 p = p4[(E_REG + c) / 4];
                s0 = fmaf(p.x, Esh[c + 0][j], s0);
                s1 = fmaf(p.y, Esh[c + 1][j], s1);
                s2 = fmaf(p.z, Esh[c + 2][j], s2);
                s3 = fmaf(p.w, Esh[c + 3][j], s3);
            }
            float ssum = (s0 + s1) + (s2 + s3);

            float cn = M + lg2f(ssum);
            if (!m) cj = cn;
            if (j == 0) Msh = cj;
            __syncthreads();
        }
        vj = cj;
    }

    // publish half-result; second arriver combines; global last reduces
    g_mid[dir][b][j] = vj;
    __threadfence();
    __syncthreads();
    if (j == 0) {
        unsigned int v = atomicAdd(&g_done[b], 1u);
        flag_sh = v;   // 1 => arrived second
    }
    __syncthreads();

    if (flag_sh == 1u) {
        __threadfence();
        float v = g_mid[0][b][j] + g_mid[1][b][j];
        red[j] = v;
        __syncthreads();
        float a0 = red[0];
        red[j] = ex2f(v - a0);
        __syncthreads();
        if (j == 0) {
            float sp = 0.f;
            for (int i = 0; i < CRF_T; i++) sp += red[i];
            float log_norm = (a0 + lg2f(sp)) / L;
            g_partial[b] = -(g_ub[b] - log_norm);
            g_done[b] = 0;            // reset for graph replay
            __threadfence();
            unsigned int c = atomicAdd(&g_count, 1u);
            flag_sh = (c == CRF_B - 1) ? 3u : 2u;
        }
        __syncthreads();

        if (flag_sh == 3u) {
            __threadfence();
            float s = 0.f;
            for (int i = j; i < CRF_B; i += CRF_T) s += g_partial[i];  // fixed order
            red[j] = s;
            __syncthreads();
            if (j == 0) {
                float tot = 0.f;
                for (int i = 0; i < CRF_T; i++) tot += red[i];
                out[0] = tot / (float)CRF_B;
                g_count = 0;          // reset for graph replay
            }
            for (int i = j; i < CRF_T * CRF_T && (1 + i) < out_size; i += CRF_T)
                out[1 + i] = trans[i];
        }
    }
}

extern "C" void kernel_launch(void* const* d_in, const int* in_sizes, int n_in,
                              void* d_out, int out_size)
{
    const float* inputs = (const float*)d_in[0];
    const float* trans  = (const float*)d_in[1];
    const unsigned char* masks = (const unsigned char*)d_in[2];
    const int* tags = (const int*)d_in[3];
    float* out = (float*)d_out;

    dim3 grid(CRF_B, 2);
    crf_scan_kernel<<<grid, CRF_T>>>(inputs, trans, masks, tags, out, out_size);
}

// round 14
// speedup vs baseline: 1.4968x; 1.4968x over previous
#include <cuda_runtime.h>
#include <cstdint>

#define CRF_B 1024
#define CRF_S 512
#define CRF_T 64
#define CRF_M 255      // forward: t in [1,255]; backward: t in [511,256]
#define CRF_PAIRS (CRF_B / 2)

// Static device scratch (no allocation)
__device__ float g_mid[2][CRF_B][CRF_T];   // base-2 log half-results
__device__ float g_ub[CRF_B];
__device__ float g_partial[CRF_B];
__device__ unsigned int g_done[CRF_PAIRS]; // zero-initialized
__device__ unsigned int g_count = 0;

__device__ __forceinline__ float ex2f(float x) {
    float y; asm("ex2.approx.ftz.f32 %0, %1;" : "=f"(y) : "f"(x)); return y;
}
__device__ __forceinline__ float lg2f(float x) {
    float y; asm("lg2.approx.f32 %0, %1;" : "=f"(y) : "f"(x)); return y;
}
__device__ __forceinline__ unsigned long long fma2(unsigned long long a,
                                                   unsigned long long b,
                                                   unsigned long long c) {
    unsigned long long d;
    asm("fma.rn.f32x2 %0, %1, %2, %3;" : "=l"(d) : "l"(a), "l"(b), "l"(c));
    return d;
}
__device__ __forceinline__ unsigned long long add2(unsigned long long a,
                                                   unsigned long long b) {
    unsigned long long d;
    asm("add.rn.f32x2 %0, %1, %2;" : "=l"(d) : "l"(a), "l"(b));
    return d;
}
__device__ __forceinline__ unsigned long long pack2(float lo, float hi) {
    unsigned long long d;
    asm("mov.b64 %0, {%1, %2};" : "=l"(d) : "f"(lo), "f"(hi));
    return d;
}
__device__ __forceinline__ void unpack2(float& lo, float& hi, unsigned long long v) {
    asm("mov.b64 {%0, %1}, %2;" : "=f"(lo), "=f"(hi) : "l"(v));
}

// grid = (512, 2). Each CTA (64 threads) runs ONE half-scan (fwd if y==0,
// bwd if y==1) for TWO batches (b0=2x, b1=2x+1). E (64 regs, f32x2-paired
// over i) is batch-invariant and shared by both recurrences, giving each
// warp two independent dependency chains per step. Log-domain (base-2)
// recurrence with thread-0 anchor, two barriers per step (R1 structure).
__global__ void __launch_bounds__(CRF_T, 8) crf_scan_kernel(
    const float* __restrict__ inputs,        // [B, S, T]
    const float* __restrict__ trans,         // [T, T]
    const unsigned char* __restrict__ masks, // [B, S]
    const int* __restrict__ tags,            // [B, S]
    float* __restrict__ out, int out_size)
{
    const int pair = blockIdx.x;
    const int dir = blockIdx.y;
    const int j = threadIdx.x;
    const int b0 = 2 * pair, b1 = 2 * pair + 1;
    const float L = 1.4426950408889634f;  // log2(e)

    __shared__ __align__(16) float pA_sh[CRF_T];
    __shared__ __align__(16) float pB_sh[CRF_T];
    __shared__ float Msh[2];
    __shared__ float red[CRF_T];
    __shared__ unsigned char maskA_sh[CRF_S];
    __shared__ unsigned char maskB_sh[CRF_S];
    __shared__ unsigned int flag_sh;

    const float* xA = inputs + (size_t)b0 * CRF_S * CRF_T;
    const float* xB = inputs + (size_t)b1 * CRF_S * CRF_T;

    for (int s = j; s < CRF_S; s += CRF_T) {
        maskA_sh[s] = masks[(size_t)b0 * CRF_S + s];
        maskB_sh[s] = masks[(size_t)b1 * CRF_S + s];
    }
    __syncthreads();

    // E2[k] = packed pair of adjacent-i entries of exp(transitions):
    //   fwd: ( e^{T[2k][j]},   e^{T[2k+1][j]} )   (column j)
    //   bwd: ( e^{T[j][2k]},   e^{T[j][2k+1]} )   (row j)
    unsigned long long E2[CRF_T / 2];
    if (dir == 0) {
#pragma unroll
        for (int k = 0; k < CRF_T / 2; k++) {
            float e0 = ex2f(L * trans[(2 * k) * CRF_T + j]);
            float e1 = ex2f(L * trans[(2 * k + 1) * CRF_T + j]);
            E2[k] = pack2(e0, e1);
        }
    } else {
#pragma unroll
        for (int k = 0; k < CRF_T / 2; k++) {
            float e0 = ex2f(L * trans[j * CRF_T + 2 * k]);
            float e1 = ex2f(L * trans[j * CRF_T + 2 * k + 1]);
            E2[k] = pack2(e0, e1);
        }
    }

    float vA, vB;  // final base-2 log elements of the two half-scans

    if (dir == 0) {
        // ---------------- forward halves (+ unary/binary for both) ----------------
        const int* tgA = tags + (size_t)b0 * CRF_S;
        const int* tgB = tags + (size_t)b1 * CRF_S;
        float ubA = 0.f, ubB = 0.f;
        for (int s = j; s < CRF_S; s += CRF_T) {
            if (!maskA_sh[s]) {
                int ts = tgA[s];
                ubA += xA[s * CRF_T + ts];
                if (s >= 1) ubA += trans[tgA[s - 1] * CRF_T + ts];
            }
            if (!maskB_sh[s]) {
                int ts = tgB[s];
                ubB += xB[s * CRF_T + ts];
                if (s >= 1) ubB += trans[tgB[s - 1] * CRF_T + ts];
            }
        }

        float bjA = L * xA[j];
        float bjB = L * xB[j];
        if (j == 0) { Msh[0] = bjA; Msh[1] = bjB; }
        __syncthreads();

        float xnA = xA[CRF_T + j];
        float xnB = xB[CRF_T + j];

#pragma unroll 1
        for (int t = 1; t <= CRF_M; t++) {
            float MA = Msh[0], MB = Msh[1];
            pA_sh[j] = ex2f(bjA - MA);
            pB_sh[j] = ex2f(bjB - MB);
            float xtA = xnA, xtB = xnB;
            unsigned char mA = maskA_sh[t], mB = maskB_sh[t];
            __syncthreads();
            if (t < CRF_M) {
                xnA = xA[(t + 1) * CRF_T + j];
                xnB = xB[(t + 1) * CRF_T + j];
            }

            const ulonglong2* qa = reinterpret_cast<const ulonglong2*>(pA_sh);
            const ulonglong2* qb = reinterpret_cast<const ulonglong2*>(pB_sh);
            unsigned long long aA0 = 0ull, aA1 = 0ull, aA2 = 0ull, aA3 = 0ull;
            unsigned long long aB0 = 0ull, aB1 = 0ull, aB2 = 0ull, aB3 = 0ull;
#pragma unroll
            for (int k = 0; k < CRF_T / 8; k++) {   // 8 iters; 2 u64-pairs per batch
                ulonglong2 va = qa[2 * k], wa = qa[2 * k + 1];
                ulonglong2 vb = qb[2 * k], wb = qb[2 * k + 1];
                aA0 = fma2(va.x, E2[4 * k + 0], aA0);
                aB0 = fma2(vb.x, E2[4 * k + 0], aB0);
                aA1 = fma2(va.y, E2[4 * k + 1], aA1);
                aB1 = fma2(vb.y, E2[4 * k + 1], aB1);
                aA2 = fma2(wa.x, E2[4 * k + 2], aA2);
                aB2 = fma2(wb.x, E2[4 * k + 2], aB2);
                aA3 = fma2(wa.y, E2[4 * k + 3], aA3);
                aB3 = fma2(wb.y, E2[4 * k + 3], aB3);
            }
            unsigned long long sA2 = add2(add2(aA0, aA1), add2(aA2, aA3));
            unsigned long long sB2 = add2(add2(aB0, aB1), add2(aB2, aB3));
            float la, ha, lb, hb;
            unpack2(la, ha, sA2);
            unpack2(lb, hb, sB2);
            float sA = la + ha, sB = lb + hb;

            float bnA = fmaf(xtA, L, MA + lg2f(sA));
            float bnB = fmaf(xtB, L, MB + lg2f(sB));
            if (!mA) bjA = bnA;
            if (!mB) bjB = bnB;
            if (j == 0) { Msh[0] = bjA; Msh[1] = bjB; }
            __syncthreads();
        }
        vA = bjA; vB = bjB;

        // stash unary+binary sums
        red[j] = ubA;
        __syncthreads();
        if (j == 0) {
            float su = 0.f;
            for (int i = 0; i < CRF_T; i++) su += red[i];
            g_ub[b0] = su;
        }
        __syncthreads();
        red[j] = ubB;
        __syncthreads();
        if (j == 0) {
            float su = 0.f;
            for (int i = 0; i < CRF_T; i++) su += red[i];
            g_ub[b1] = su;
        }
    } else {
        // ---------------- backward halves ----------------
        float cjA = 0.f, cjB = 0.f;
        if (j == 0) { Msh[0] = 0.f; Msh[1] = 0.f; }
        __syncthreads();

        float xnA = xA[(CRF_S - 1) * CRF_T + j];
        float xnB = xB[(CRF_S - 1) * CRF_T + j];

#pragma unroll 1
        for (int t = CRF_S - 1; t > CRF_M; t--) {
            float MA = Msh[0], MB = Msh[1];
            float xtA = xnA, xtB = xnB;
            unsigned char mA = maskA_sh[t], mB = maskB_sh[t];
            pA_sh[j] = ex2f(fmaf(L, xtA, cjA - MA));
            pB_sh[j] = ex2f(fmaf(L, xtB, cjB - MB));
            __syncthreads();
            if (t > CRF_M + 1) {
                xnA = xA[(t - 1) * CRF_T + j];
                xnB = xB[(t - 1) * CRF_T + j];
            }

            const ulonglong2* qa = reinterpret_cast<const ulonglong2*>(pA_sh);
            const ulonglong2* qb = reinterpret_cast<const ulonglong2*>(pB_sh);
            unsigned long long aA0 = 0ull, aA1 = 0ull, aA2 = 0ull, aA3 = 0ull;
            unsigned long long aB0 = 0ull, aB1 = 0ull, aB2 = 0ull, aB3 = 0ull;
#pragma unroll
            for (int k = 0; k < CRF_T / 8; k++) {
                ulonglong2 va = qa[2 * k], wa = qa[2 * k + 1];
                ulonglong2 vb = qb[2 * k], wb = qb[2 * k + 1];
                aA0 = fma2(va.x, E2[4 * k + 0], aA0);
                aB0 = fma2(vb.x, E2[4 * k + 0], aB0);
                aA1 = fma2(va.y, E2[4 * k + 1], aA1);
                aB1 = fma2(vb.y, E2[4 * k + 1], aB1);
                aA2 = fma2(wa.x, E2[4 * k + 2], aA2);
                aB2 = fma2(wb.x, E2[4 * k + 2], aB2);
                aA3 = fma2(wa.y, E2[4 * k + 3], aA3);
                aB3 = fma2(wb.y, E2[4 * k + 3], aB3);
            }
            unsigned long long sA2 = add2(add2(aA0, aA1), add2(aA2, aA3));
            unsigned long long sB2 = add2(add2(aB0, aB1), add2(aB2, aB3));
            float la, ha, lb, hb;
            unpack2(la, ha, sA2);
            unpack2(lb, hb, sB2);
            float sA = la + ha, sB = lb + hb;

            float cnA = MA + lg2f(sA);
            float cnB = MB + lg2f(sB);
            if (!mA) cjA = cnA;
            if (!mB) cjB = cnB;
            if (j == 0) { Msh[0] = cjA; Msh[1] = cjB; }
            __syncthreads();
        }
        vA = cjA; vB = cjB;
    }

    // publish half-results; second arriver per pair combines; global last reduces
    g_mid[dir][b0][j] = vA;
    g_mid[dir][b1][j] = vB;
    __threadfence();
    __syncthreads();
    if (j == 0) {
        unsigned int v = atomicAdd(&g_done[pair], 1u);
        flag_sh = v;   // 1 => arrived second
    }
    __syncthreads();

    if (flag_sh == 1u) {
        __threadfence();
        const float L2 = 1.4426950408889634f;
#pragma unroll 1
        for (int bb = 0; bb < 2; bb++) {
            int b = (bb == 0) ? b0 : b1;
            float v = g_mid[0][b][j] + g_mid[1][b][j];
            red[j] = v;
            __syncthreads();
            float a0 = red[0];
            red[j] = ex2f(v - a0);
            __syncthreads();
            if (j == 0) {
                float sp = 0.f;
                for (int i = 0; i < CRF_T; i++) sp += red[i];
                float log_norm = (a0 + lg2f(sp)) / L2;
                g_partial[b] = -(g_ub[b] - log_norm);
            }
            __syncthreads();
        }
        if (j == 0) {
            g_done[pair] = 0;          // reset for graph replay
            __threadfence();
            unsigned int c = atomicAdd(&g_count, 1u);
            flag_sh = (c == CRF_PAIRS - 1) ? 3u : 2u;
        }
        __syncthreads();

        if (flag_sh == 3u) {
            __threadfence();
            float s = 0.f;
            for (int i = j; i < CRF_B; i += CRF_T) s += g_partial[i];  // fixed order
            red[j] = s;
            __syncthreads();
            if (j == 0) {
                float tot = 0.f;
                for (int i = 0; i < CRF_T; i++) tot += red[i];
                out[0] = tot / (float)CRF_B;
                g_count = 0;           // reset for graph replay
            }
            for (int i = j; i < CRF_T * CRF_T && (1 + i) < out_size; i += CRF_T)
                out[1 + i] = trans[i];
        }
    }
}

extern "C" void kernel_launch(void* const* d_in, const int* in_sizes, int n_in,
                              void* d_out, int out_size)
{
    const float* inputs = (const float*)d_in[0];
    const float* trans  = (const float*)d_in[1];
    const unsigned char* masks = (const unsigned char*)d_in[2];
    const int* tags = (const int*)d_in[3];
    float* out = (float*)d_out;

    dim3 grid(CRF_PAIRS, 2);
    crf_scan_kernel<<<grid, CRF_T>>>(inputs, trans, masks, tags, out, out_size);
}